// round 1
// baseline (speedup 1.0000x reference)
#include <cuda_runtime.h>
#include <cstddef>

// Problem dims
constexpr int B_   = 2;
constexpr int SEQ  = 2048;
constexpr int DM   = 1024;   // d_model
constexpr int NH   = 16;     // heads
constexpr int DH   = 64;     // d_head
constexpr int MROWS = B_ * SEQ;          // 4096
constexpr size_t QKV_ELEMS = (size_t)B_ * NH * SEQ * DH;  // 4,194,304

// Scratch (device globals; no runtime allocation)
__device__ float g_q[QKV_ELEMS];
__device__ float g_k[QKV_ELEMS];
__device__ float g_v[QKV_ELEMS];
__device__ float g_z[QKV_ELEMS];   // [b, s, h, e] == row-major [4096, 1024]

// ---------------------------------------------------------------------------
// Kernel 1: fused QKV projection.
// GEMM: A = x [4096, 1024] row-major, Bmat = W_{q,k,v} [H, D, E] viewed as
// [K=1024, N=1024] with col c = h*64+e. Output -> g_{q,k,v} in [B,H,S,E].
// Tiling: BM=BN=128, BK=8, 256 threads, 8x8 register tile, reg prefetch.
// ---------------------------------------------------------------------------
__global__ __launch_bounds__(256) void qkv_gemm_kernel(
    const float* __restrict__ x,
    const float* __restrict__ Wq, const float* __restrict__ bq,
    const float* __restrict__ Wk, const float* __restrict__ bk,
    const float* __restrict__ Wv, const float* __restrict__ bv)
{
    __shared__ float As[8][128];
    __shared__ float Bs[8][128];

    const int pz = blockIdx.z;
    const float* W    = (pz == 0) ? Wq : (pz == 1) ? Wk : Wv;
    const float* bias = (pz == 0) ? bq : (pz == 1) ? bk : bv;
    float* outp       = (pz == 0) ? g_q : (pz == 1) ? g_k : g_v;

    const int n0 = blockIdx.x * 128;
    const int m0 = blockIdx.y * 128;
    const int tid = threadIdx.x;
    const int tx = tid & 15;
    const int ty = tid >> 4;

    // A-load mapping: 128 rows x 2 half-rows of 4 (float4 along k)
    const int lm  = tid >> 1;           // 0..127
    const int lkq = (tid & 1) * 4;      // 0 or 4
    // B-load mapping: 8 k-rows x 32 col-quads
    const int lbk = tid >> 5;           // 0..7
    const int lbn = (tid & 31) * 4;     // 0..124
    const int bc  = n0 + lbn;
    const int bh  = bc >> 6;            // head for this column quad (const per thread)
    const int be  = bc & 63;
    const float* Wbase = W + (size_t)bh * DM * DH + be;
    const float* Abase = x + (size_t)(m0 + lm) * DM + lkq;

    float acc[8][8];
#pragma unroll
    for (int i = 0; i < 8; i++)
#pragma unroll
        for (int j = 0; j < 8; j++) acc[i][j] = 0.0f;

    // prefetch first tile
    float4 pa = *(const float4*)(Abase);
    float4 pb = *(const float4*)(Wbase + (size_t)lbk * DH);

    for (int kt = 0; kt < DM / 8; kt++) {
        As[lkq + 0][lm] = pa.x;
        As[lkq + 1][lm] = pa.y;
        As[lkq + 2][lm] = pa.z;
        As[lkq + 3][lm] = pa.w;
        *(float4*)&Bs[lbk][lbn] = pb;
        __syncthreads();

        if (kt < DM / 8 - 1) {
            int k0n = (kt + 1) * 8;
            pa = *(const float4*)(Abase + k0n);
            pb = *(const float4*)(Wbase + (size_t)(k0n + lbk) * DH);
        }

#pragma unroll
        for (int kk = 0; kk < 8; kk++) {
            float4 a0 = *(const float4*)&As[kk][ty * 8];
            float4 a1 = *(const float4*)&As[kk][ty * 8 + 4];
            float4 b0 = *(const float4*)&Bs[kk][tx * 8];
            float4 b1 = *(const float4*)&Bs[kk][tx * 8 + 4];
            float av[8] = {a0.x, a0.y, a0.z, a0.w, a1.x, a1.y, a1.z, a1.w};
            float bv8[8] = {b0.x, b0.y, b0.z, b0.w, b1.x, b1.y, b1.z, b1.w};
#pragma unroll
            for (int i = 0; i < 8; i++)
#pragma unroll
                for (int j = 0; j < 8; j++)
                    acc[i][j] = fmaf(av[i], bv8[j], acc[i][j]);
        }
        __syncthreads();
    }

    // Epilogue: out[((b*NH+h)*SEQ+s)*DH + e] = acc + bias[c]
#pragma unroll
    for (int i = 0; i < 8; i++) {
        int mg = m0 + ty * 8 + i;
        int bb = mg >> 11;           // / SEQ
        int ss = mg & (SEQ - 1);
#pragma unroll
        for (int j4 = 0; j4 < 8; j4 += 4) {
            int c = n0 + tx * 8 + j4;
            int h = c >> 6;
            int e = c & 63;
            float4 w;
            w.x = acc[i][j4 + 0] + bias[c + 0];
            w.y = acc[i][j4 + 1] + bias[c + 1];
            w.z = acc[i][j4 + 2] + bias[c + 2];
            w.w = acc[i][j4 + 3] + bias[c + 3];
            *(float4*)(outp + ((((size_t)bb * NH + h) * SEQ + ss) * DH + e)) = w;
        }
    }
}

// ---------------------------------------------------------------------------
// Kernel 2: causal flash attention over q/k/v in [B,H,S,E].
// Block: 128 queries x (loop over 64-key tiles). 256 threads, 8x4 reg tile.
// Writes z in [b, s, h, e] layout for the output projection.
// ---------------------------------------------------------------------------
constexpr int QT_LD = 132;  // 128 + 4 pad  (16B-aligned row: 132*4=528)
constexpr int KT_LD = 68;   // 64 + 4 pad
constexpr int SMEM_FLASH_FLOATS = 64 * QT_LD      /* Qt [e][q] */
                                + 64 * KT_LD      /* Kt [e][k] */
                                + 64 * KT_LD      /* Vs [k][d] */
                                + 64 * QT_LD      /* St [k][q] */
                                + 3 * 128;        /* m, l, rescale */
constexpr size_t SMEM_FLASH_BYTES = SMEM_FLASH_FLOATS * sizeof(float);

__global__ __launch_bounds__(256) void flash_attn_kernel()
{
    extern __shared__ float sm[];
    float* Qt  = sm;                      // [64][QT_LD]  (e-major)
    float* Kt  = Qt + 64 * QT_LD;         // [64][KT_LD]  (e-major)
    float* Vs  = Kt + 64 * KT_LD;         // [64][KT_LD]  (k-major, natural)
    float* St  = Vs + 64 * KT_LD;         // [64][QT_LD]  (k-major: St[k][q])
    float* m_s = St + 64 * QT_LD;         // [128]
    float* l_s = m_s + 128;               // [128]
    float* r_s = l_s + 128;               // [128]

    const int bhid  = blockIdx.y;                      // 0..31
    const int itile = (gridDim.x - 1) - blockIdx.x;    // heavy q-tiles first
    const int q0    = itile * 128;
    const float* Qg = g_q + (size_t)bhid * SEQ * DH;
    const float* Kg = g_k + (size_t)bhid * SEQ * DH;
    const float* Vg = g_v + (size_t)bhid * SEQ * DH;

    const int tid = threadIdx.x;
    const int tx = tid & 15;   // key/dim group (x4)
    const int ty = tid >> 4;   // query group (x8)

    // Load Q tile transposed: Qt[e][q]
    {
        int q = tid & 127;
        int half = tid >> 7;
        const float* src = Qg + (size_t)(q0 + q) * DH + half * 32;
#pragma unroll
        for (int i = 0; i < 8; i++) {
            float4 v = *(const float4*)(src + i * 4);
            int e = half * 32 + i * 4;
            Qt[(e + 0) * QT_LD + q] = v.x;
            Qt[(e + 1) * QT_LD + q] = v.y;
            Qt[(e + 2) * QT_LD + q] = v.z;
            Qt[(e + 3) * QT_LD + q] = v.w;
        }
    }
    if (tid < 128) { m_s[tid] = -3.0e38f; l_s[tid] = 0.0f; }

    float o[8][4];
#pragma unroll
    for (int i = 0; i < 8; i++)
#pragma unroll
        for (int j = 0; j < 4; j++) o[i][j] = 0.0f;

    __syncthreads();

    const int jmax = 2 * itile + 1;
    for (int j = 0; j <= jmax; j++) {
        const int k0 = j * 64;

        // Load K (transposed) and V (natural) tiles
        {
            int k = tid & 63;
            int grp = tid >> 6;   // 0..3
            const float* ksrc = Kg + (size_t)(k0 + k) * DH + grp * 16;
            const float* vsrc = Vg + (size_t)(k0 + k) * DH + grp * 16;
#pragma unroll
            for (int i = 0; i < 4; i++) {
                int e = grp * 16 + i * 4;
                float4 kv = *(const float4*)(ksrc + i * 4);
                Kt[(e + 0) * KT_LD + k] = kv.x;
                Kt[(e + 1) * KT_LD + k] = kv.y;
                Kt[(e + 2) * KT_LD + k] = kv.z;
                Kt[(e + 3) * KT_LD + k] = kv.w;
                float4 vv = *(const float4*)(vsrc + i * 4);
                *(float4*)&Vs[k * KT_LD + e] = vv;
            }
        }
        __syncthreads();

        // Phase A: S = Q K^T  (scaled), write transposed St[k][q]
        float s[8][4];
#pragma unroll
        for (int i = 0; i < 8; i++)
#pragma unroll
            for (int jj = 0; jj < 4; jj++) s[i][jj] = 0.0f;

#pragma unroll 4
        for (int e = 0; e < 64; e++) {
            float4 a0 = *(const float4*)&Qt[e * QT_LD + ty * 8];
            float4 a1 = *(const float4*)&Qt[e * QT_LD + ty * 8 + 4];
            float4 b  = *(const float4*)&Kt[e * KT_LD + tx * 4];
            float av[8] = {a0.x, a0.y, a0.z, a0.w, a1.x, a1.y, a1.z, a1.w};
            float bv4[4] = {b.x, b.y, b.z, b.w};
#pragma unroll
            for (int i = 0; i < 8; i++)
#pragma unroll
                for (int jj = 0; jj < 4; jj++)
                    s[i][jj] = fmaf(av[i], bv4[jj], s[i][jj]);
        }

        const bool maskTile = (j >= 2 * itile);
#pragma unroll
        for (int jj = 0; jj < 4; jj++) {
            int kg = k0 + tx * 4 + jj;
#pragma unroll
            for (int i = 0; i < 8; i++) {
                int qg = q0 + ty * 8 + i;
                float v = s[i][jj] * 0.125f;   // 1/sqrt(64)
                if (maskTile && (kg > qg)) v = -1.0e30f;
                St[(tx * 4 + jj) * QT_LD + (ty * 8 + i)] = v;
            }
        }
        __syncthreads();

        // Phase B: online softmax per query row (one thread per row)
        if (tid < 128) {
            int r = tid;
            float mo = m_s[r];
            float mx = mo;
#pragma unroll 8
            for (int k = 0; k < 64; k++) mx = fmaxf(mx, St[k * QT_LD + r]);
            float sc = __expf(mo - mx);
            float sum = 0.0f;
#pragma unroll 8
            for (int k = 0; k < 64; k++) {
                float p = __expf(St[k * QT_LD + r] - mx);
                St[k * QT_LD + r] = p;
                sum += p;
            }
            m_s[r] = mx;
            l_s[r] = l_s[r] * sc + sum;
            r_s[r] = sc;
        }
        __syncthreads();

        // Phase C: O = O*rescale + P @ V
        float rs[8];
#pragma unroll
        for (int i = 0; i < 8; i++) rs[i] = r_s[ty * 8 + i];
#pragma unroll
        for (int i = 0; i < 8; i++)
#pragma unroll
            for (int jj = 0; jj < 4; jj++) o[i][jj] *= rs[i];

#pragma unroll 4
        for (int k = 0; k < 64; k++) {
            float4 a0 = *(const float4*)&St[k * QT_LD + ty * 8];
            float4 a1 = *(const float4*)&St[k * QT_LD + ty * 8 + 4];
            float4 b  = *(const float4*)&Vs[k * KT_LD + tx * 4];
            float av[8] = {a0.x, a0.y, a0.z, a0.w, a1.x, a1.y, a1.z, a1.w};
            float bv4[4] = {b.x, b.y, b.z, b.w};
#pragma unroll
            for (int i = 0; i < 8; i++)
#pragma unroll
                for (int jj = 0; jj < 4; jj++)
                    o[i][jj] = fmaf(av[i], bv4[jj], o[i][jj]);
        }
        __syncthreads();
    }

    // Epilogue: z[b, q, h, :] = o / l
    const int bb = bhid >> 4;
    const int h  = bhid & 15;
#pragma unroll
    for (int i = 0; i < 8; i++) {
        int q = ty * 8 + i;
        float li = 1.0f / l_s[q];
        float4 w;
        w.x = o[i][0] * li;
        w.y = o[i][1] * li;
        w.z = o[i][2] * li;
        w.w = o[i][3] * li;
        size_t idx = (((size_t)bb * SEQ + (q0 + q)) * NH + h) * DH + tx * 4;
        *(float4*)(g_z + idx) = w;
    }
}

// ---------------------------------------------------------------------------
// Kernel 3: output projection.  out = z[4096,1024] @ W_O[1024,1024] + b_O
// (W_O [H,E,D] flat is exactly row-major [K=1024, N=1024])
// ---------------------------------------------------------------------------
__global__ __launch_bounds__(256) void out_gemm_kernel(
    const float* __restrict__ WO, const float* __restrict__ bO,
    float* __restrict__ out)
{
    __shared__ float As[8][128];
    __shared__ float Bs[8][128];

    const int n0 = blockIdx.x * 128;
    const int m0 = blockIdx.y * 128;
    const int tid = threadIdx.x;
    const int tx = tid & 15;
    const int ty = tid >> 4;

    const int lm  = tid >> 1;
    const int lkq = (tid & 1) * 4;
    const int lbk = tid >> 5;
    const int lbn = (tid & 31) * 4;
    const float* Abase = g_z + (size_t)(m0 + lm) * DM + lkq;
    const float* Bbase = WO + (size_t)lbk * DM + n0 + lbn;

    float acc[8][8];
#pragma unroll
    for (int i = 0; i < 8; i++)
#pragma unroll
        for (int j = 0; j < 8; j++) acc[i][j] = 0.0f;

    float4 pa = *(const float4*)(Abase);
    float4 pb = *(const float4*)(Bbase);

    for (int kt = 0; kt < DM / 8; kt++) {
        As[lkq + 0][lm] = pa.x;
        As[lkq + 1][lm] = pa.y;
        As[lkq + 2][lm] = pa.z;
        As[lkq + 3][lm] = pa.w;
        *(float4*)&Bs[lbk][lbn] = pb;
        __syncthreads();

        if (kt < DM / 8 - 1) {
            int k0n = (kt + 1) * 8;
            pa = *(const float4*)(Abase + k0n);
            pb = *(const float4*)(Bbase + (size_t)k0n * DM);
        }

#pragma unroll
        for (int kk = 0; kk < 8; kk++) {
            float4 a0 = *(const float4*)&As[kk][ty * 8];
            float4 a1 = *(const float4*)&As[kk][ty * 8 + 4];
            float4 b0 = *(const float4*)&Bs[kk][tx * 8];
            float4 b1 = *(const float4*)&Bs[kk][tx * 8 + 4];
            float av[8] = {a0.x, a0.y, a0.z, a0.w, a1.x, a1.y, a1.z, a1.w};
            float bv8[8] = {b0.x, b0.y, b0.z, b0.w, b1.x, b1.y, b1.z, b1.w};
#pragma unroll
            for (int i = 0; i < 8; i++)
#pragma unroll
                for (int j = 0; j < 8; j++)
                    acc[i][j] = fmaf(av[i], bv8[j], acc[i][j]);
        }
        __syncthreads();
    }

#pragma unroll
    for (int i = 0; i < 8; i++) {
        size_t mg = m0 + ty * 8 + i;
#pragma unroll
        for (int j4 = 0; j4 < 8; j4 += 4) {
            int c = n0 + tx * 8 + j4;
            float4 w;
            w.x = acc[i][j4 + 0] + bO[c + 0];
            w.y = acc[i][j4 + 1] + bO[c + 1];
            w.z = acc[i][j4 + 2] + bO[c + 2];
            w.w = acc[i][j4 + 3] + bO[c + 3];
            *(float4*)(out + mg * DM + c) = w;
        }
    }
}

// ---------------------------------------------------------------------------
// Launch
// inputs: 0=x, 1=W_Q, 2=b_Q, 3=W_K, 4=b_K, 5=W_V, 6=b_V, 7=W_O, 8=b_O
// ---------------------------------------------------------------------------
extern "C" void kernel_launch(void* const* d_in, const int* in_sizes, int n_in,
                              void* d_out, int out_size)
{
    const float* x  = (const float*)d_in[0];
    const float* Wq = (const float*)d_in[1];
    const float* bq = (const float*)d_in[2];
    const float* Wk = (const float*)d_in[3];
    const float* bk = (const float*)d_in[4];
    const float* Wv = (const float*)d_in[5];
    const float* bv = (const float*)d_in[6];
    const float* Wo = (const float*)d_in[7];
    const float* bo = (const float*)d_in[8];
    float* out = (float*)d_out;

    cudaFuncSetAttribute(flash_attn_kernel,
                         cudaFuncAttributeMaxDynamicSharedMemorySize,
                         (int)SMEM_FLASH_BYTES);

    dim3 g1(DM / 128, MROWS / 128, 3);   // (8, 32, 3)
    qkv_gemm_kernel<<<g1, 256>>>(x, Wq, bq, Wk, bk, Wv, bv);

    dim3 g2(SEQ / 128, B_ * NH);          // (16, 32)
    flash_attn_kernel<<<g2, 256, SMEM_FLASH_BYTES>>>();

    dim3 g3(DM / 128, MROWS / 128);       // (8, 32)
    out_gemm_kernel<<<g3, 256>>>(Wo, bo, out);
}

// round 2
// speedup vs baseline: 2.5213x; 2.5213x over previous
#include <cuda_runtime.h>
#include <cstddef>

// Problem dims
constexpr int B_   = 2;
constexpr int SEQ  = 2048;
constexpr int DM   = 1024;   // d_model
constexpr int NH   = 16;     // heads
constexpr int DH   = 64;     // d_head
constexpr int MROWS = B_ * SEQ;          // 4096
constexpr size_t QKV_ELEMS = (size_t)B_ * NH * SEQ * DH;  // 4,194,304

// Scratch (device globals; no runtime allocation)
__device__ float g_q[QKV_ELEMS];   // [B,H,S,E]
__device__ float g_k[QKV_ELEMS];
__device__ float g_v[QKV_ELEMS];
__device__ float g_z[QKV_ELEMS];   // [b, s, h, e] == row-major [4096, 1024]

// ---------------------------------------------------------------------------
// tf32 helpers
// ---------------------------------------------------------------------------
__device__ __forceinline__ float f2tf(float f) {
    unsigned u;
    asm("cvt.rna.tf32.f32 %0, %1;" : "=r"(u) : "f"(f));
    return __uint_as_float(u);
}

__device__ __forceinline__ void mma_tf32(float* c,
                                         unsigned a0, unsigned a1, unsigned a2, unsigned a3,
                                         unsigned b0, unsigned b1) {
    asm("mma.sync.aligned.m16n8k8.row.col.f32.tf32.tf32.f32 "
        "{%0,%1,%2,%3}, {%4,%5,%6,%7}, {%8,%9}, {%0,%1,%2,%3};"
        : "+f"(c[0]), "+f"(c[1]), "+f"(c[2]), "+f"(c[3])
        : "r"(a0), "r"(a1), "r"(a2), "r"(a3), "r"(b0), "r"(b1));
}

// ---------------------------------------------------------------------------
// Kernel 1: fused QKV projection (tf32 tensor cores).
// A = x [4096, 1024] fp32 row-major; B column c = h*64+e -> W[h][d][e].
// BM=BN=128, BK=32, 8 warps in 2(m) x 4(n); warp tile 64x32 (4x4 mma tiles).
// ---------------------------------------------------------------------------
__global__ __launch_bounds__(256, 2) void qkv_gemm_tc(
    const float* __restrict__ x,
    const float* __restrict__ Wq, const float* __restrict__ bq,
    const float* __restrict__ Wk, const float* __restrict__ bk,
    const float* __restrict__ Wv, const float* __restrict__ bv)
{
    __shared__ float As[128][36];   // [m][k], pad -> bank(4m+k): conflict-free frag loads
    __shared__ float Bs[32][136];   // [k][n], pad -> bank(8k+n): conflict-free frag loads

    const int pz = blockIdx.z;
    const float* W    = (pz == 0) ? Wq : (pz == 1) ? Wk : Wv;
    const float* bias = (pz == 0) ? bq : (pz == 1) ? bk : bv;
    float* outp       = (pz == 0) ? g_q : (pz == 1) ? g_k : g_v;

    const int n0 = blockIdx.x * 128;
    const int m0 = blockIdx.y * 128;
    const int tid  = threadIdx.x;
    const int wid  = tid >> 5;
    const int lane = tid & 31;
    const int wm = wid >> 2;      // 0..1
    const int wn = wid & 3;       // 0..3
    const int g  = lane >> 2;     // groupID
    const int t  = lane & 3;      // threadID_in_group

    // global loaders
    const int arow = tid >> 3;          // 0..31 (+32p)
    const int akq  = (tid & 7) * 4;     // k-quad within 32
    const int brow = tid >> 5;          // 0..7 (+8p)
    const int bnq  = (tid & 31) * 4;    // n-quad within 128
    const int cb = n0 + bnq;
    const int hh = cb >> 6;
    const int ee = cb & 63;
    const float* Wbase = W + ((size_t)hh * DM) * DH + ee;
    const float* Abase = x + (size_t)m0 * DM;

    float acc[4][4][4] = {};

    for (int kt = 0; kt < DM / 32; ++kt) {
        const int kb = kt * 32;
#pragma unroll
        for (int p = 0; p < 4; p++) {
            int r = p * 32 + arow;
            float4 v = *(const float4*)(Abase + (size_t)r * DM + kb + akq);
            float4 c; c.x = f2tf(v.x); c.y = f2tf(v.y); c.z = f2tf(v.z); c.w = f2tf(v.w);
            *(float4*)&As[r][akq] = c;
        }
#pragma unroll
        for (int p = 0; p < 4; p++) {
            int kr = p * 8 + brow;
            float4 v = *(const float4*)(Wbase + (size_t)(kb + kr) * DH);
            float4 c; c.x = f2tf(v.x); c.y = f2tf(v.y); c.z = f2tf(v.z); c.w = f2tf(v.w);
            *(float4*)&Bs[kr][bnq] = c;
        }
        __syncthreads();

#pragma unroll
        for (int ch = 0; ch < 4; ch++) {
            const int ks = ch * 8;
            unsigned a[4][4], b[4][2];
#pragma unroll
            for (int mt = 0; mt < 4; mt++) {
                int r = wm * 64 + mt * 16 + g;
                a[mt][0] = __float_as_uint(As[r][ks + t]);
                a[mt][1] = __float_as_uint(As[r + 8][ks + t]);
                a[mt][2] = __float_as_uint(As[r][ks + t + 4]);
                a[mt][3] = __float_as_uint(As[r + 8][ks + t + 4]);
            }
#pragma unroll
            for (int nt = 0; nt < 4; nt++) {
                int cn = wn * 32 + nt * 8 + g;
                b[nt][0] = __float_as_uint(Bs[ks + t][cn]);
                b[nt][1] = __float_as_uint(Bs[ks + t + 4][cn]);
            }
#pragma unroll
            for (int mt = 0; mt < 4; mt++)
#pragma unroll
                for (int nt = 0; nt < 4; nt++)
                    mma_tf32(acc[mt][nt], a[mt][0], a[mt][1], a[mt][2], a[mt][3],
                             b[nt][0], b[nt][1]);
        }
        __syncthreads();
    }

    // Epilogue: out[((b*NH+h)*SEQ+s)*DH + e] = acc + bias[c]
#pragma unroll
    for (int mt = 0; mt < 4; mt++) {
#pragma unroll
        for (int nt = 0; nt < 4; nt++) {
            int mg = m0 + wm * 64 + mt * 16 + g;
            int c  = n0 + wn * 32 + nt * 8 + t * 2;
            int h  = c >> 6;
            int e  = c & 63;
            float b0 = bias[c], b1 = bias[c + 1];
#pragma unroll
            for (int rr = 0; rr < 2; rr++) {
                int mgr = mg + rr * 8;
                int bb = mgr >> 11;
                int ss = mgr & (SEQ - 1);
                float2 w;
                w.x = acc[mt][nt][rr * 2 + 0] + b0;
                w.y = acc[mt][nt][rr * 2 + 1] + b1;
                *(float2*)(outp + ((((size_t)bb * NH + h) * SEQ + ss) * DH + e)) = w;
            }
        }
    }
}

// ---------------------------------------------------------------------------
// Kernel 2: causal flash attention, tf32 MMA for QK^T and PV, fp32 softmax.
// Block: 128 queries x 64-key tiles. 8 warps in 4(q) x 2(k/e).
// ---------------------------------------------------------------------------
constexpr int QS_LD = 68;
constexpr int KV_LD = 72;
constexpr int ST_LD = 136;
constexpr int SMEM_FLASH_FLOATS = 128 * QS_LD   /* Qs [q][e]  */
                                + 64 * KV_LD    /* Kt [e][k]  */
                                + 64 * KV_LD    /* Vs [k][e]  */
                                + 64 * ST_LD    /* St [k][q]  */
                                + 3 * 128;
constexpr size_t SMEM_FLASH_BYTES = SMEM_FLASH_FLOATS * sizeof(float);

__global__ __launch_bounds__(256, 2) void flash_attn_tc()
{
    extern __shared__ float smf[];
    float* Qs  = smf;                    // [128][QS_LD]  row q, col e (tf32)
    float* Kt  = Qs + 128 * QS_LD;       // [64][KV_LD]   row e, col k (tf32)
    float* Vs  = Kt + 64 * KV_LD;        // [64][KV_LD]   row k, col e (tf32)
    float* St  = Vs + 64 * KV_LD;        // [64][ST_LD]   row k, col q (fp32 then tf32)
    float* m_s = St + 64 * ST_LD;
    float* l_s = m_s + 128;
    float* r_s = l_s + 128;

    const int bhid  = blockIdx.y;                   // 0..31
    const int itile = (gridDim.x - 1) - blockIdx.x; // heavy q-tiles first
    const int q0    = itile * 128;
    const float* Qg = g_q + (size_t)bhid * SEQ * DH;
    const float* Kg = g_k + (size_t)bhid * SEQ * DH;
    const float* Vg = g_v + (size_t)bhid * SEQ * DH;

    const int tid  = threadIdx.x;
    const int wid  = tid >> 5;
    const int lane = tid & 31;
    const int wy = wid >> 1;   // 0..3 (q)
    const int wx = wid & 1;    // 0..1 (k or e)
    const int g  = lane >> 2;
    const int t  = lane & 3;

    // Load Q (scaled by 1/sqrt(64), tf32)
    {
        int q  = tid >> 1;
        int eh = (tid & 1) * 32;
        const float* src = Qg + (size_t)(q0 + q) * DH + eh;
#pragma unroll
        for (int i = 0; i < 8; i++) {
            float4 v = ((const float4*)src)[i];
            float4 c;
            c.x = f2tf(v.x * 0.125f); c.y = f2tf(v.y * 0.125f);
            c.z = f2tf(v.z * 0.125f); c.w = f2tf(v.w * 0.125f);
            *(float4*)&Qs[q * QS_LD + eh + i * 4] = c;
        }
    }
    if (tid < 128) { m_s[tid] = -3.0e38f; l_s[tid] = 0.0f; }

    float o[2][4][4] = {};

    __syncthreads();

    const int jmax = 2 * itile + 1;
    for (int j = 0; j <= jmax; j++) {
        const int k0 = j * 64;

        // Load K (transposed [e][k]) and V (natural [k][e]) as tf32
        {
            int kk  = tid & 63;
            int grp = tid >> 6;
            const float* ksrc = Kg + (size_t)(k0 + kk) * DH + grp * 16;
            const float* vsrc = Vg + (size_t)(k0 + kk) * DH + grp * 16;
#pragma unroll
            for (int i = 0; i < 4; i++) {
                int e = grp * 16 + i * 4;
                float4 kv = ((const float4*)ksrc)[i];
                Kt[(e + 0) * KV_LD + kk] = f2tf(kv.x);
                Kt[(e + 1) * KV_LD + kk] = f2tf(kv.y);
                Kt[(e + 2) * KV_LD + kk] = f2tf(kv.z);
                Kt[(e + 3) * KV_LD + kk] = f2tf(kv.w);
                float4 vv = ((const float4*)vsrc)[i];
                float4 c;
                c.x = f2tf(vv.x); c.y = f2tf(vv.y); c.z = f2tf(vv.z); c.w = f2tf(vv.w);
                *(float4*)&Vs[kk * KV_LD + e] = c;
            }
        }
        __syncthreads();

        // Phase A: S = Q K^T  (warp tile 32q x 32k; 2 mt x 4 nt)
        float s[2][4][4] = {};
#pragma unroll
        for (int ec = 0; ec < 8; ec++) {
            const int ks = ec * 8;
            unsigned a[2][4], b[4][2];
#pragma unroll
            for (int mt = 0; mt < 2; mt++) {
                int r = wy * 32 + mt * 16 + g;
                a[mt][0] = __float_as_uint(Qs[r * QS_LD + ks + t]);
                a[mt][1] = __float_as_uint(Qs[(r + 8) * QS_LD + ks + t]);
                a[mt][2] = __float_as_uint(Qs[r * QS_LD + ks + t + 4]);
                a[mt][3] = __float_as_uint(Qs[(r + 8) * QS_LD + ks + t + 4]);
            }
#pragma unroll
            for (int nt = 0; nt < 4; nt++) {
                int kc = wx * 32 + nt * 8 + g;
                b[nt][0] = __float_as_uint(Kt[(ks + t) * KV_LD + kc]);
                b[nt][1] = __float_as_uint(Kt[(ks + t + 4) * KV_LD + kc]);
            }
#pragma unroll
            for (int mt = 0; mt < 2; mt++)
#pragma unroll
                for (int nt = 0; nt < 4; nt++)
                    mma_tf32(s[mt][nt], a[mt][0], a[mt][1], a[mt][2], a[mt][3],
                             b[nt][0], b[nt][1]);
        }

        // Mask + store S transposed to St[k][q] (fp32)
        const bool maskTile = (j >= 2 * itile);
#pragma unroll
        for (int mt = 0; mt < 2; mt++) {
#pragma unroll
            for (int nt = 0; nt < 4; nt++) {
                int qr = wy * 32 + mt * 16 + g;
                int kc = wx * 32 + nt * 8 + t * 2;
#pragma unroll
                for (int rr = 0; rr < 2; rr++) {
#pragma unroll
                    for (int cc = 0; cc < 2; cc++) {
                        int qrl = qr + rr * 8;
                        int kcl = kc + cc;
                        float v = s[mt][nt][rr * 2 + cc];
                        if (maskTile && (k0 + kcl > q0 + qrl)) v = -1.0e30f;
                        St[kcl * ST_LD + qrl] = v;
                    }
                }
            }
        }
        __syncthreads();

        // Phase B: online softmax per query row; writes tf32(p) back to St
        if (tid < 128) {
            int r = tid;
            float mo = m_s[r];
            float mx = mo;
#pragma unroll 8
            for (int k = 0; k < 64; k++) mx = fmaxf(mx, St[k * ST_LD + r]);
            float sc = __expf(mo - mx);
            float sum = 0.0f;
#pragma unroll 8
            for (int k = 0; k < 64; k++) {
                float p = __expf(St[k * ST_LD + r] - mx);
                St[k * ST_LD + r] = f2tf(p);
                sum += p;
            }
            m_s[r] = mx;
            l_s[r] = l_s[r] * sc + sum;
            r_s[r] = sc;
        }
        __syncthreads();

        // Phase C: O = O*rescale + P @ V  (warp tile 32q x 32e)
#pragma unroll
        for (int mt = 0; mt < 2; mt++) {
            float rs0 = r_s[wy * 32 + mt * 16 + g];
            float rs1 = r_s[wy * 32 + mt * 16 + g + 8];
#pragma unroll
            for (int nt = 0; nt < 4; nt++) {
                o[mt][nt][0] *= rs0; o[mt][nt][1] *= rs0;
                o[mt][nt][2] *= rs1; o[mt][nt][3] *= rs1;
            }
        }
#pragma unroll
        for (int kc = 0; kc < 8; kc++) {
            const int ks = kc * 8;
            unsigned a[2][4], b[4][2];
#pragma unroll
            for (int mt = 0; mt < 2; mt++) {
                int r = wy * 32 + mt * 16 + g;
                a[mt][0] = __float_as_uint(St[(ks + t) * ST_LD + r]);
                a[mt][1] = __float_as_uint(St[(ks + t) * ST_LD + r + 8]);
                a[mt][2] = __float_as_uint(St[(ks + t + 4) * ST_LD + r]);
                a[mt][3] = __float_as_uint(St[(ks + t + 4) * ST_LD + r + 8]);
            }
#pragma unroll
            for (int nt = 0; nt < 4; nt++) {
                int en = wx * 32 + nt * 8 + g;
                b[nt][0] = __float_as_uint(Vs[(ks + t) * KV_LD + en]);
                b[nt][1] = __float_as_uint(Vs[(ks + t + 4) * KV_LD + en]);
            }
#pragma unroll
            for (int mt = 0; mt < 2; mt++)
#pragma unroll
                for (int nt = 0; nt < 4; nt++)
                    mma_tf32(o[mt][nt], a[mt][0], a[mt][1], a[mt][2], a[mt][3],
                             b[nt][0], b[nt][1]);
        }
        __syncthreads();
    }

    // Epilogue: z[b, q, h, e] = o / l
    const int bb = bhid >> 4;
    const int h  = bhid & 15;
#pragma unroll
    for (int mt = 0; mt < 2; mt++) {
        int qr = wy * 32 + mt * 16 + g;
        float li0 = 1.0f / l_s[qr];
        float li1 = 1.0f / l_s[qr + 8];
#pragma unroll
        for (int nt = 0; nt < 4; nt++) {
            int e = wx * 32 + nt * 8 + t * 2;
            float2 w0, w1;
            w0.x = o[mt][nt][0] * li0; w0.y = o[mt][nt][1] * li0;
            w1.x = o[mt][nt][2] * li1; w1.y = o[mt][nt][3] * li1;
            size_t i0 = (((size_t)bb * SEQ + (q0 + qr)) * NH + h) * DH + e;
            size_t i1 = (((size_t)bb * SEQ + (q0 + qr + 8)) * NH + h) * DH + e;
            *(float2*)(g_z + i0) = w0;
            *(float2*)(g_z + i1) = w1;
        }
    }
}

// ---------------------------------------------------------------------------
// Kernel 3: output projection (tf32).  out = z[4096,1024] @ W_O[1024,1024] + b_O
// ---------------------------------------------------------------------------
__global__ __launch_bounds__(256, 2) void out_gemm_tc(
    const float* __restrict__ WO, const float* __restrict__ bO,
    float* __restrict__ out)
{
    __shared__ float As[128][36];
    __shared__ float Bs[32][136];

    const int n0 = blockIdx.x * 128;
    const int m0 = blockIdx.y * 128;
    const int tid  = threadIdx.x;
    const int wid  = tid >> 5;
    const int lane = tid & 31;
    const int wm = wid >> 2;
    const int wn = wid & 3;
    const int g  = lane >> 2;
    const int t  = lane & 3;

    const int arow = tid >> 3;
    const int akq  = (tid & 7) * 4;
    const int brow = tid >> 5;
    const int bnq  = (tid & 31) * 4;
    const float* Abase = g_z + (size_t)m0 * DM;
    const float* Bbase = WO + n0 + bnq;

    float acc[4][4][4] = {};

    for (int kt = 0; kt < DM / 32; ++kt) {
        const int kb = kt * 32;
#pragma unroll
        for (int p = 0; p < 4; p++) {
            int r = p * 32 + arow;
            float4 v = *(const float4*)(Abase + (size_t)r * DM + kb + akq);
            float4 c; c.x = f2tf(v.x); c.y = f2tf(v.y); c.z = f2tf(v.z); c.w = f2tf(v.w);
            *(float4*)&As[r][akq] = c;
        }
#pragma unroll
        for (int p = 0; p < 4; p++) {
            int kr = p * 8 + brow;
            float4 v = *(const float4*)(Bbase + (size_t)(kb + kr) * DM);
            float4 c; c.x = f2tf(v.x); c.y = f2tf(v.y); c.z = f2tf(v.z); c.w = f2tf(v.w);
            *(float4*)&Bs[kr][bnq] = c;
        }
        __syncthreads();

#pragma unroll
        for (int ch = 0; ch < 4; ch++) {
            const int ks = ch * 8;
            unsigned a[4][4], b[4][2];
#pragma unroll
            for (int mt = 0; mt < 4; mt++) {
                int r = wm * 64 + mt * 16 + g;
                a[mt][0] = __float_as_uint(As[r][ks + t]);
                a[mt][1] = __float_as_uint(As[r + 8][ks + t]);
                a[mt][2] = __float_as_uint(As[r][ks + t + 4]);
                a[mt][3] = __float_as_uint(As[r + 8][ks + t + 4]);
            }
#pragma unroll
            for (int nt = 0; nt < 4; nt++) {
                int cn = wn * 32 + nt * 8 + g;
                b[nt][0] = __float_as_uint(Bs[ks + t][cn]);
                b[nt][1] = __float_as_uint(Bs[ks + t + 4][cn]);
            }
#pragma unroll
            for (int mt = 0; mt < 4; mt++)
#pragma unroll
                for (int nt = 0; nt < 4; nt++)
                    mma_tf32(acc[mt][nt], a[mt][0], a[mt][1], a[mt][2], a[mt][3],
                             b[nt][0], b[nt][1]);
        }
        __syncthreads();
    }

#pragma unroll
    for (int mt = 0; mt < 4; mt++) {
#pragma unroll
        for (int nt = 0; nt < 4; nt++) {
            int mg = m0 + wm * 64 + mt * 16 + g;
            int c  = n0 + wn * 32 + nt * 8 + t * 2;
            float b0 = bO[c], b1 = bO[c + 1];
#pragma unroll
            for (int rr = 0; rr < 2; rr++) {
                float2 w;
                w.x = acc[mt][nt][rr * 2 + 0] + b0;
                w.y = acc[mt][nt][rr * 2 + 1] + b1;
                *(float2*)(out + (size_t)(mg + rr * 8) * DM + c) = w;
            }
        }
    }
}

// ---------------------------------------------------------------------------
// Launch
// inputs: 0=x, 1=W_Q, 2=b_Q, 3=W_K, 4=b_K, 5=W_V, 6=b_V, 7=W_O, 8=b_O
// ---------------------------------------------------------------------------
extern "C" void kernel_launch(void* const* d_in, const int* in_sizes, int n_in,
                              void* d_out, int out_size)
{
    const float* x  = (const float*)d_in[0];
    const float* Wq = (const float*)d_in[1];
    const float* bq = (const float*)d_in[2];
    const float* Wk = (const float*)d_in[3];
    const float* bk = (const float*)d_in[4];
    const float* Wv = (const float*)d_in[5];
    const float* bv = (const float*)d_in[6];
    const float* Wo = (const float*)d_in[7];
    const float* bo = (const float*)d_in[8];
    float* out = (float*)d_out;

    cudaFuncSetAttribute(flash_attn_tc,
                         cudaFuncAttributeMaxDynamicSharedMemorySize,
                         (int)SMEM_FLASH_BYTES);

    dim3 g1(DM / 128, MROWS / 128, 3);   // (8, 32, 3)
    qkv_gemm_tc<<<g1, 256>>>(x, Wq, bq, Wk, bk, Wv, bv);

    dim3 g2(SEQ / 128, B_ * NH);          // (16, 32)
    flash_attn_tc<<<g2, 256, SMEM_FLASH_BYTES>>>();

    dim3 g3(DM / 128, MROWS / 128);       // (8, 32)
    out_gemm_tc<<<g3, 256>>>(Wo, bo, out);
}

// round 3
// speedup vs baseline: 2.7355x; 1.0850x over previous
#include <cuda_runtime.h>
#include <cstddef>

// Problem dims
constexpr int B_   = 2;
constexpr int SEQ  = 2048;
constexpr int DM   = 1024;   // d_model
constexpr int NH   = 16;     // heads
constexpr int DH   = 64;     // d_head
constexpr int MROWS = B_ * SEQ;          // 4096
constexpr size_t QKV_ELEMS = (size_t)B_ * NH * SEQ * DH;  // 4,194,304

// Scratch (device globals; no runtime allocation)
__device__ float g_q[QKV_ELEMS];   // [B,H,S,E]
__device__ float g_k[QKV_ELEMS];
__device__ float g_v[QKV_ELEMS];
__device__ float g_z[QKV_ELEMS];   // [b, s, h, e] == row-major [4096, 1024]

// ---------------------------------------------------------------------------
// tf32 helpers
// ---------------------------------------------------------------------------
__device__ __forceinline__ float f2tf(float f) {
    unsigned u;
    asm("cvt.rna.tf32.f32 %0, %1;" : "=r"(u) : "f"(f));
    return __uint_as_float(u);
}

__device__ __forceinline__ void mma_tf32(float* c,
                                         unsigned a0, unsigned a1, unsigned a2, unsigned a3,
                                         unsigned b0, unsigned b1) {
    asm("mma.sync.aligned.m16n8k8.row.col.f32.tf32.tf32.f32 "
        "{%0,%1,%2,%3}, {%4,%5,%6,%7}, {%8,%9}, {%0,%1,%2,%3};"
        : "+f"(c[0]), "+f"(c[1]), "+f"(c[2]), "+f"(c[3])
        : "r"(a0), "r"(a1), "r"(a2), "r"(a3), "r"(b0), "r"(b1));
}

// ---------------------------------------------------------------------------
// Kernel 1: fused QKV projection (tf32, register-prefetched k-tiles).
// BM=BN=128, BK=32, 8 warps in 2(m) x 4(n); warp tile 64x32 (4x4 mma tiles).
// ---------------------------------------------------------------------------
__global__ __launch_bounds__(256, 2) void qkv_gemm_tc(
    const float* __restrict__ x,
    const float* __restrict__ Wq, const float* __restrict__ bq,
    const float* __restrict__ Wk, const float* __restrict__ bk,
    const float* __restrict__ Wv, const float* __restrict__ bv)
{
    __shared__ float As[128][36];   // [m][k]
    __shared__ float Bs[32][136];   // [k][n]

    const int pz = blockIdx.z;
    const float* W    = (pz == 0) ? Wq : (pz == 1) ? Wk : Wv;
    const float* bias = (pz == 0) ? bq : (pz == 1) ? bk : bv;
    float* outp       = (pz == 0) ? g_q : (pz == 1) ? g_k : g_v;

    const int n0 = blockIdx.x * 128;
    const int m0 = blockIdx.y * 128;
    const int tid  = threadIdx.x;
    const int wid  = tid >> 5;
    const int lane = tid & 31;
    const int wm = wid >> 2;
    const int wn = wid & 3;
    const int g  = lane >> 2;
    const int t  = lane & 3;

    const int arow = tid >> 3;
    const int akq  = (tid & 7) * 4;
    const int brow = tid >> 5;
    const int bnq  = (tid & 31) * 4;
    const int cb = n0 + bnq;
    const int hh = cb >> 6;
    const int ee = cb & 63;
    const float* Wbase = W + ((size_t)hh * DM) * DH + ee;
    const float* Abase = x + (size_t)m0 * DM;

    float acc[4][4][4] = {};
    float4 pa[4], pb[4];

    // prefetch tile 0
#pragma unroll
    for (int p = 0; p < 4; p++)
        pa[p] = *(const float4*)(Abase + (size_t)(p * 32 + arow) * DM + akq);
#pragma unroll
    for (int p = 0; p < 4; p++)
        pb[p] = *(const float4*)(Wbase + (size_t)(p * 8 + brow) * DH);

    for (int kt = 0; kt < DM / 32; ++kt) {
#pragma unroll
        for (int p = 0; p < 4; p++) {
            float4 c; c.x = f2tf(pa[p].x); c.y = f2tf(pa[p].y);
            c.z = f2tf(pa[p].z); c.w = f2tf(pa[p].w);
            *(float4*)&As[p * 32 + arow][akq] = c;
        }
#pragma unroll
        for (int p = 0; p < 4; p++) {
            float4 c; c.x = f2tf(pb[p].x); c.y = f2tf(pb[p].y);
            c.z = f2tf(pb[p].z); c.w = f2tf(pb[p].w);
            *(float4*)&Bs[p * 8 + brow][bnq] = c;
        }
        __syncthreads();

        if (kt < DM / 32 - 1) {
            const int kb = (kt + 1) * 32;
#pragma unroll
            for (int p = 0; p < 4; p++)
                pa[p] = *(const float4*)(Abase + (size_t)(p * 32 + arow) * DM + kb + akq);
#pragma unroll
            for (int p = 0; p < 4; p++)
                pb[p] = *(const float4*)(Wbase + (size_t)(kb + p * 8 + brow) * DH);
        }

#pragma unroll
        for (int ch = 0; ch < 4; ch++) {
            const int ks = ch * 8;
            unsigned a[4][4];
#pragma unroll
            for (int mt = 0; mt < 4; mt++) {
                int r = wm * 64 + mt * 16 + g;
                a[mt][0] = __float_as_uint(As[r][ks + t]);
                a[mt][1] = __float_as_uint(As[r + 8][ks + t]);
                a[mt][2] = __float_as_uint(As[r][ks + t + 4]);
                a[mt][3] = __float_as_uint(As[r + 8][ks + t + 4]);
            }
#pragma unroll
            for (int nt = 0; nt < 4; nt++) {
                int cn = wn * 32 + nt * 8 + g;
                unsigned b0 = __float_as_uint(Bs[ks + t][cn]);
                unsigned b1 = __float_as_uint(Bs[ks + t + 4][cn]);
#pragma unroll
                for (int mt = 0; mt < 4; mt++)
                    mma_tf32(acc[mt][nt], a[mt][0], a[mt][1], a[mt][2], a[mt][3], b0, b1);
            }
        }
        __syncthreads();
    }

#pragma unroll
    for (int mt = 0; mt < 4; mt++) {
#pragma unroll
        for (int nt = 0; nt < 4; nt++) {
            int mg = m0 + wm * 64 + mt * 16 + g;
            int c  = n0 + wn * 32 + nt * 8 + t * 2;
            int h  = c >> 6;
            int e  = c & 63;
            float b0 = bias[c], b1 = bias[c + 1];
#pragma unroll
            for (int rr = 0; rr < 2; rr++) {
                int mgr = mg + rr * 8;
                int bb = mgr >> 11;
                int ss = mgr & (SEQ - 1);
                float2 w;
                w.x = acc[mt][nt][rr * 2 + 0] + b0;
                w.y = acc[mt][nt][rr * 2 + 1] + b1;
                *(float2*)(outp + ((((size_t)bb * NH + h) * SEQ + ss) * DH + e)) = w;
            }
        }
    }
}

// ---------------------------------------------------------------------------
// Kernel 2: causal flash attention, tf32 MMA, register softmax.
// 8 warps; warp w owns query rows [w*16, w*16+16) x all 64 keys of the tile.
// Q fragments hoisted to registers; Qs smem reused as P buffer.
// ---------------------------------------------------------------------------
constexpr int QS_LD = 68;
constexpr int KV_LD = 72;
constexpr int SMEM_FLASH_FLOATS = 128 * QS_LD    /* Qs / Ps */
                                + 64 * KV_LD     /* Kt [e][k] */
                                + 64 * KV_LD;    /* Vs [k][e] */
constexpr size_t SMEM_FLASH_BYTES = SMEM_FLASH_FLOATS * sizeof(float);

__global__ __launch_bounds__(256, 2) void flash_attn_tc()
{
    extern __shared__ float smf[];
    float* Qs = smf;                    // [128][QS_LD], later aliased as Ps
    float* Kt = Qs + 128 * QS_LD;       // [64][KV_LD]  row e, col k
    float* Vs = Kt + 64 * KV_LD;        // [64][KV_LD]  row k, col e

    const int bhid  = blockIdx.y;
    const int itile = (gridDim.x - 1) - blockIdx.x;  // heavy q-tiles first
    const int q0    = itile * 128;
    const float* Qg = g_q + (size_t)bhid * SEQ * DH;
    const float* Kg = g_k + (size_t)bhid * SEQ * DH;
    const float* Vg = g_v + (size_t)bhid * SEQ * DH;

    const int tid  = threadIdx.x;
    const int wid  = tid >> 5;
    const int lane = tid & 31;
    const int g  = lane >> 2;
    const int t  = lane & 3;
    const int r0 = wid * 16 + g;    // local q rows owned by this thread
    const int r1 = r0 + 8;

    // --- load Q (scaled, tf32) into Qs ---
    {
        int q  = tid >> 1;
        int eh = (tid & 1) * 32;
        const float* src = Qg + (size_t)(q0 + q) * DH + eh;
#pragma unroll
        for (int i = 0; i < 8; i++) {
            float4 v = ((const float4*)src)[i];
            float4 c;
            c.x = f2tf(v.x * 0.125f); c.y = f2tf(v.y * 0.125f);
            c.z = f2tf(v.z * 0.125f); c.w = f2tf(v.w * 0.125f);
            *(float4*)&Qs[q * QS_LD + eh + i * 4] = c;
        }
    }

    // --- load K/V tile j=0 ---
    const int kk  = tid & 63;
    const int grp = tid >> 6;
    const float* Kgl = Kg + (size_t)kk * DH + grp * 16;
    const float* Vgl = Vg + (size_t)kk * DH + grp * 16;
    {
#pragma unroll
        for (int i = 0; i < 4; i++) {
            int e = grp * 16 + i * 4;
            float4 kv = ((const float4*)Kgl)[i];
            Kt[(e + 0) * KV_LD + kk] = f2tf(kv.x);
            Kt[(e + 1) * KV_LD + kk] = f2tf(kv.y);
            Kt[(e + 2) * KV_LD + kk] = f2tf(kv.z);
            Kt[(e + 3) * KV_LD + kk] = f2tf(kv.w);
            float4 vv = ((const float4*)Vgl)[i];
            float4 c; c.x = f2tf(vv.x); c.y = f2tf(vv.y);
            c.z = f2tf(vv.z); c.w = f2tf(vv.w);
            *(float4*)&Vs[kk * KV_LD + e] = c;
        }
    }
    __syncthreads();

    // --- hoist Q fragments into registers; Qs becomes Ps ---
    unsigned qf[8][4];
#pragma unroll
    for (int ec = 0; ec < 8; ec++) {
        const int ks = ec * 8;
        qf[ec][0] = __float_as_uint(Qs[r0 * QS_LD + ks + t]);
        qf[ec][1] = __float_as_uint(Qs[r1 * QS_LD + ks + t]);
        qf[ec][2] = __float_as_uint(Qs[r0 * QS_LD + ks + t + 4]);
        qf[ec][3] = __float_as_uint(Qs[r1 * QS_LD + ks + t + 4]);
    }
    float* Ps = Qs;

    float m0 = -3.0e38f, m1 = -3.0e38f, l0 = 0.0f, l1 = 0.0f;
    float o[8][4] = {};

    const int jmax = 2 * itile + 1;
    for (int j = 0; j <= jmax; j++) {
        const int k0 = j * 64;

        // ---- Phase A: S = Q K^T  (16q x 64k per warp) ----
        float s[8][4] = {};
#pragma unroll
        for (int ec = 0; ec < 8; ec++) {
            const int ks = ec * 8;
#pragma unroll
            for (int nt = 0; nt < 8; nt++) {
                unsigned b0 = __float_as_uint(Kt[(ks + t) * KV_LD + nt * 8 + g]);
                unsigned b1 = __float_as_uint(Kt[(ks + t + 4) * KV_LD + nt * 8 + g]);
                mma_tf32(s[nt], qf[ec][0], qf[ec][1], qf[ec][2], qf[ec][3], b0, b1);
            }
        }

        // ---- mask ----
        if (j >= 2 * itile) {
            const int qg0 = q0 + r0, qg1 = q0 + r1;
#pragma unroll
            for (int nt = 0; nt < 8; nt++) {
#pragma unroll
                for (int cc = 0; cc < 2; cc++) {
                    int kg = k0 + nt * 8 + t * 2 + cc;
                    if (kg > qg0) s[nt][cc]     = -1.0e30f;
                    if (kg > qg1) s[nt][2 + cc] = -1.0e30f;
                }
            }
        }

        // ---- register online softmax (quad reductions) ----
        float mx0 = -3.0e38f, mx1 = -3.0e38f;
#pragma unroll
        for (int nt = 0; nt < 8; nt++) {
            mx0 = fmaxf(mx0, fmaxf(s[nt][0], s[nt][1]));
            mx1 = fmaxf(mx1, fmaxf(s[nt][2], s[nt][3]));
        }
        mx0 = fmaxf(mx0, __shfl_xor_sync(0xFFFFFFFFu, mx0, 1));
        mx0 = fmaxf(mx0, __shfl_xor_sync(0xFFFFFFFFu, mx0, 2));
        mx1 = fmaxf(mx1, __shfl_xor_sync(0xFFFFFFFFu, mx1, 1));
        mx1 = fmaxf(mx1, __shfl_xor_sync(0xFFFFFFFFu, mx1, 2));
        mx0 = fmaxf(mx0, m0);
        mx1 = fmaxf(mx1, m1);
        const float sc0 = __expf(m0 - mx0);
        const float sc1 = __expf(m1 - mx1);
        m0 = mx0; m1 = mx1;

        float sum0 = 0.0f, sum1 = 0.0f;
#pragma unroll
        for (int nt = 0; nt < 8; nt++) {
            s[nt][0] = __expf(s[nt][0] - mx0);
            s[nt][1] = __expf(s[nt][1] - mx0);
            s[nt][2] = __expf(s[nt][2] - mx1);
            s[nt][3] = __expf(s[nt][3] - mx1);
            sum0 += s[nt][0] + s[nt][1];
            sum1 += s[nt][2] + s[nt][3];
        }
        sum0 += __shfl_xor_sync(0xFFFFFFFFu, sum0, 1);
        sum0 += __shfl_xor_sync(0xFFFFFFFFu, sum0, 2);
        sum1 += __shfl_xor_sync(0xFFFFFFFFu, sum1, 1);
        sum1 += __shfl_xor_sync(0xFFFFFFFFu, sum1, 2);
        l0 = l0 * sc0 + sum0;
        l1 = l1 * sc1 + sum1;

        // ---- store P (tf32) to per-warp rows of Ps ----
#pragma unroll
        for (int nt = 0; nt < 8; nt++) {
            const int kc = nt * 8 + t * 2;
            Ps[r0 * QS_LD + kc]     = f2tf(s[nt][0]);
            Ps[r0 * QS_LD + kc + 1] = f2tf(s[nt][1]);
            Ps[r1 * QS_LD + kc]     = f2tf(s[nt][2]);
            Ps[r1 * QS_LD + kc + 1] = f2tf(s[nt][3]);
        }
        __syncwarp();

        // ---- rescale O ----
#pragma unroll
        for (int nt = 0; nt < 8; nt++) {
            o[nt][0] *= sc0; o[nt][1] *= sc0;
            o[nt][2] *= sc1; o[nt][3] *= sc1;
        }

        // ---- prefetch next K/V tile into registers ----
        float4 pk[4], pv[4];
        if (j < jmax) {
            const size_t off = (size_t)(k0 + 64) * DH;
#pragma unroll
            for (int i = 0; i < 4; i++) {
                pk[i] = ((const float4*)(Kgl + off))[i];
                pv[i] = ((const float4*)(Vgl + off))[i];
            }
        }

        // ---- Phase C: O += P V  (16q x 64e per warp) ----
#pragma unroll
        for (int kc = 0; kc < 8; kc++) {
            const int ks = kc * 8;
            unsigned a0 = __float_as_uint(Ps[r0 * QS_LD + ks + t]);
            unsigned a1 = __float_as_uint(Ps[r1 * QS_LD + ks + t]);
            unsigned a2 = __float_as_uint(Ps[r0 * QS_LD + ks + t + 4]);
            unsigned a3 = __float_as_uint(Ps[r1 * QS_LD + ks + t + 4]);
#pragma unroll
            for (int nt = 0; nt < 8; nt++) {
                unsigned b0 = __float_as_uint(Vs[(ks + t) * KV_LD + nt * 8 + g]);
                unsigned b1 = __float_as_uint(Vs[(ks + t + 4) * KV_LD + nt * 8 + g]);
                mma_tf32(o[nt], a0, a1, a2, a3, b0, b1);
            }
        }

        // ---- commit prefetched K/V ----
        if (j < jmax) {
            __syncthreads();
#pragma unroll
            for (int i = 0; i < 4; i++) {
                int e = grp * 16 + i * 4;
                Kt[(e + 0) * KV_LD + kk] = f2tf(pk[i].x);
                Kt[(e + 1) * KV_LD + kk] = f2tf(pk[i].y);
                Kt[(e + 2) * KV_LD + kk] = f2tf(pk[i].z);
                Kt[(e + 3) * KV_LD + kk] = f2tf(pk[i].w);
                float4 c; c.x = f2tf(pv[i].x); c.y = f2tf(pv[i].y);
                c.z = f2tf(pv[i].z); c.w = f2tf(pv[i].w);
                *(float4*)&Vs[kk * KV_LD + e] = c;
            }
            __syncthreads();
        }
    }

    // ---- epilogue: z[b, q, h, e] = o / l ----
    const int bb = bhid >> 4;
    const int h  = bhid & 15;
    const float li0 = 1.0f / l0;
    const float li1 = 1.0f / l1;
#pragma unroll
    for (int nt = 0; nt < 8; nt++) {
        const int e = nt * 8 + t * 2;
        float2 w0, w1;
        w0.x = o[nt][0] * li0; w0.y = o[nt][1] * li0;
        w1.x = o[nt][2] * li1; w1.y = o[nt][3] * li1;
        size_t i0 = (((size_t)bb * SEQ + (q0 + r0)) * NH + h) * DH + e;
        size_t i1 = (((size_t)bb * SEQ + (q0 + r1)) * NH + h) * DH + e;
        *(float2*)(g_z + i0) = w0;
        *(float2*)(g_z + i1) = w1;
    }
}

// ---------------------------------------------------------------------------
// Kernel 3: output projection (tf32, register-prefetched).
// ---------------------------------------------------------------------------
__global__ __launch_bounds__(256, 2) void out_gemm_tc(
    const float* __restrict__ WO, const float* __restrict__ bO,
    float* __restrict__ out)
{
    __shared__ float As[128][36];
    __shared__ float Bs[32][136];

    const int n0 = blockIdx.x * 128;
    const int m0 = blockIdx.y * 128;
    const int tid  = threadIdx.x;
    const int wid  = tid >> 5;
    const int lane = tid & 31;
    const int wm = wid >> 2;
    const int wn = wid & 3;
    const int g  = lane >> 2;
    const int t  = lane & 3;

    const int arow = tid >> 3;
    const int akq  = (tid & 7) * 4;
    const int brow = tid >> 5;
    const int bnq  = (tid & 31) * 4;
    const float* Abase = g_z + (size_t)m0 * DM;
    const float* Bbase = WO + n0 + bnq;

    float acc[4][4][4] = {};
    float4 pa[4], pb[4];

#pragma unroll
    for (int p = 0; p < 4; p++)
        pa[p] = *(const float4*)(Abase + (size_t)(p * 32 + arow) * DM + akq);
#pragma unroll
    for (int p = 0; p < 4; p++)
        pb[p] = *(const float4*)(Bbase + (size_t)(p * 8 + brow) * DM);

    for (int kt = 0; kt < DM / 32; ++kt) {
#pragma unroll
        for (int p = 0; p < 4; p++) {
            float4 c; c.x = f2tf(pa[p].x); c.y = f2tf(pa[p].y);
            c.z = f2tf(pa[p].z); c.w = f2tf(pa[p].w);
            *(float4*)&As[p * 32 + arow][akq] = c;
        }
#pragma unroll
        for (int p = 0; p < 4; p++) {
            float4 c; c.x = f2tf(pb[p].x); c.y = f2tf(pb[p].y);
            c.z = f2tf(pb[p].z); c.w = f2tf(pb[p].w);
            *(float4*)&Bs[p * 8 + brow][bnq] = c;
        }
        __syncthreads();

        if (kt < DM / 32 - 1) {
            const int kb = (kt + 1) * 32;
#pragma unroll
            for (int p = 0; p < 4; p++)
                pa[p] = *(const float4*)(Abase + (size_t)(p * 32 + arow) * DM + kb + akq);
#pragma unroll
            for (int p = 0; p < 4; p++)
                pb[p] = *(const float4*)(Bbase + (size_t)(kb + p * 8 + brow) * DM);
        }

#pragma unroll
        for (int ch = 0; ch < 4; ch++) {
            const int ks = ch * 8;
            unsigned a[4][4];
#pragma unroll
            for (int mt = 0; mt < 4; mt++) {
                int r = wm * 64 + mt * 16 + g;
                a[mt][0] = __float_as_uint(As[r][ks + t]);
                a[mt][1] = __float_as_uint(As[r + 8][ks + t]);
                a[mt][2] = __float_as_uint(As[r][ks + t + 4]);
                a[mt][3] = __float_as_uint(As[r + 8][ks + t + 4]);
            }
#pragma unroll
            for (int nt = 0; nt < 4; nt++) {
                int cn = wn * 32 + nt * 8 + g;
                unsigned b0 = __float_as_uint(Bs[ks + t][cn]);
                unsigned b1 = __float_as_uint(Bs[ks + t + 4][cn]);
#pragma unroll
                for (int mt = 0; mt < 4; mt++)
                    mma_tf32(acc[mt][nt], a[mt][0], a[mt][1], a[mt][2], a[mt][3], b0, b1);
            }
        }
        __syncthreads();
    }

#pragma unroll
    for (int mt = 0; mt < 4; mt++) {
#pragma unroll
        for (int nt = 0; nt < 4; nt++) {
            int mg = m0 + wm * 64 + mt * 16 + g;
            int c  = n0 + wn * 32 + nt * 8 + t * 2;
            float b0 = bO[c], b1 = bO[c + 1];
#pragma unroll
            for (int rr = 0; rr < 2; rr++) {
                float2 w;
                w.x = acc[mt][nt][rr * 2 + 0] + b0;
                w.y = acc[mt][nt][rr * 2 + 1] + b1;
                *(float2*)(out + (size_t)(mg + rr * 8) * DM + c) = w;
            }
        }
    }
}

// ---------------------------------------------------------------------------
// Launch
// inputs: 0=x, 1=W_Q, 2=b_Q, 3=W_K, 4=b_K, 5=W_V, 6=b_V, 7=W_O, 8=b_O
// ---------------------------------------------------------------------------
extern "C" void kernel_launch(void* const* d_in, const int* in_sizes, int n_in,
                              void* d_out, int out_size)
{
    const float* x  = (const float*)d_in[0];
    const float* Wq = (const float*)d_in[1];
    const float* bq = (const float*)d_in[2];
    const float* Wk = (const float*)d_in[3];
    const float* bk = (const float*)d_in[4];
    const float* Wv = (const float*)d_in[5];
    const float* bv = (const float*)d_in[6];
    const float* Wo = (const float*)d_in[7];
    const float* bo = (const float*)d_in[8];
    float* out = (float*)d_out;

    cudaFuncSetAttribute(flash_attn_tc,
                         cudaFuncAttributeMaxDynamicSharedMemorySize,
                         (int)SMEM_FLASH_BYTES);

    dim3 g1(DM / 128, MROWS / 128, 3);   // (8, 32, 3)
    qkv_gemm_tc<<<g1, 256>>>(x, Wq, bq, Wk, bk, Wv, bv);

    dim3 g2(SEQ / 128, B_ * NH);          // (16, 32)
    flash_attn_tc<<<g2, 256, SMEM_FLASH_BYTES>>>();

    dim3 g3(DM / 128, MROWS / 128);       // (8, 32)
    out_gemm_tc<<<g3, 256>>>(Wo, bo, out);
}